// round 5
// baseline (speedup 1.0000x reference)
#include <cuda_runtime.h>
#include <float.h>

#define N_COLS   32000
#define NV4      (N_COLS / 4)      // 8000; last partial iter is warp-uniform (warps 0,1)
#define THREADS  256
#define NWARPS   (THREADS / 32)
#define SEG_CAP  640               // per-warp candidate capacity (SMEM path)
#define NR       16                // per-thread register cache => reg path <= 512/warp
#define MAX_ROWS 4096
#define BITERS   26

__device__ float g_row_loss[MAX_ROWS];

// Order-preserving float<->int maps (monotone bijection) for atomicMax on floats.
__device__ __forceinline__ int f2ord(float f) {
    int i = __float_as_int(f);
    return (i >= 0) ? i : (i ^ 0x7fffffff);
}
__device__ __forceinline__ float ord2f(int i) {
    return __int_as_float((i >= 0) ? i : (i ^ 0x7fffffff));
}

__global__ void __launch_bounds__(THREADS, 4)
entmax15_rows(const float* __restrict__ inp, const int* __restrict__ tgt) {
    __shared__ float scand[NWARPS * SEG_CAP];   // 20 KB
    __shared__ int   wcnt[NWARPS];
    __shared__ float red[3 * NWARPS];
    __shared__ int   s_max;                     // running block max (ordered-int)

    const int row  = blockIdx.x;
    const int tid  = threadIdx.x;
    const int lane = tid & 31;
    const int w    = tid >> 5;
    const float* rp = inp + (size_t)row * N_COLS;
    const float4* g4 = (const float4*)rp;

    if (tid == 0) s_max = f2ord(-FLT_MAX);
    __syncthreads();

    // ---- Single DRAM pass: running-max threshold + optimistic compaction ----
    // Exact rule needs final max m: keep v >= m - 2. Any lower bound lb <= m
    // gives a SAFE filter (v >= lb - 2 is a superset). False accepts have
    // X = (v-m)/2 < -1 and contribute 0 in all later math.
    int cw = 0;
    for (int i = tid; i < NV4; i += THREADS) {
        float4 v = g4[i];
        // warp batch max -> merge into block running max
        float bm = fmaxf(fmaxf(v.x, v.y), fmaxf(v.z, v.w));
        #pragma unroll
        for (int o = 16; o; o >>= 1) bm = fmaxf(bm, __shfl_xor_sync(0xffffffffu, bm, o));
        int cur;
        if (lane == 0) {
            int me  = f2ord(bm);
            int old = atomicMax(&s_max, me);
            cur = (old > me) ? old : me;        // >= own batch AND >= block max at this point
        }
        cur = __shfl_sync(0xffffffffu, cur, 0);
        const float thr = ord2f(cur) - 2.0f;

        float xs[4] = {v.x, v.y, v.z, v.w};
        #pragma unroll
        for (int c = 0; c < 4; ++c) {
            bool p = xs[c] >= thr;
            unsigned b = __ballot_sync(0xffffffffu, p);
            if (p) {
                int pos = cw + __popc(b & ((1u << lane) - 1u));
                if (pos < SEG_CAP) scand[w * SEG_CAP + pos] = xs[c];   // raw v
            }
            cw += __popc(b);
        }
    }
    if (lane == 0) wcnt[w] = cw;
    __syncthreads();

    const float m = ord2f(s_max);   // exact row max now
    bool ovf = false;
    #pragma unroll
    for (int k = 0; k < NWARPS; ++k) ovf |= (wcnt[k] > SEG_CAP);

    const int ti = tgt[row];
    const float tg_logit = __ldg(rp + ((ti < 0) ? 0 : (ti >= N_COLS ? N_COLS - 1 : ti)));

    if (!ovf) {
        // ---- Block-wide bisection on cached candidates ----
        const int mycw = wcnt[w];
        float xc[NR];
        int nm = 0;
        const bool cached = (mycw <= 32 * NR);
        if (cached)
            for (int i = lane; i < mycw; i += 32)
                xc[nm++] = (scand[w * SEG_CAP + i] - m) * 0.5f;

        float lo = -1.0f, hi = 0.0f;
        for (int it = 0; it < BITERS; ++it) {
            float mid = 0.5f * (lo + hi);
            float s = 0.0f;
            if (cached) {
                #pragma unroll
                for (int j = 0; j < NR; ++j)
                    if (j < nm) { float d = xc[j] - mid; if (d > 0.0f) s = fmaf(d, d, s); }
            } else {
                for (int i = lane; i < mycw; i += 32) {
                    float d = (scand[w * SEG_CAP + i] - m) * 0.5f - mid;
                    if (d > 0.0f) s = fmaf(d, d, s);
                }
            }
            #pragma unroll
            for (int o = 16; o; o >>= 1) s += __shfl_xor_sync(0xffffffffu, s, o);
            if (lane == 0) red[w] = s;
            __syncthreads();
            float tot = 0.0f;
            #pragma unroll
            for (int k = 0; k < NWARPS; ++k) tot += red[k];
            __syncthreads();
            if (tot >= 1.0f) lo = mid; else hi = mid;   // uniform across block
        }
        const float tau = 0.5f * (lo + hi);

        // ---- Final sums (deterministic order) ----
        float sp = 0.0f, s15 = 0.0f, spx = 0.0f;
        if (cached) {
            #pragma unroll
            for (int j = 0; j < NR; ++j)
                if (j < nm) {
                    float x = xc[j], d = x - tau;
                    if (d > 0.0f) { float p = d * d; sp += p; s15 = fmaf(p, d, s15); spx = fmaf(p, x, spx); }
                }
        } else {
            for (int i = lane; i < mycw; i += 32) {
                float x = (scand[w * SEG_CAP + i] - m) * 0.5f, d = x - tau;
                if (d > 0.0f) { float p = d * d; sp += p; s15 = fmaf(p, d, s15); spx = fmaf(p, x, spx); }
            }
        }
        #pragma unroll
        for (int o = 16; o; o >>= 1) {
            sp  += __shfl_xor_sync(0xffffffffu, sp,  o);
            s15 += __shfl_xor_sync(0xffffffffu, s15, o);
            spx += __shfl_xor_sync(0xffffffffu, spx, o);
        }
        if (lane == 0) { red[w] = sp; red[NWARPS + w] = s15; red[2 * NWARPS + w] = spx; }
        __syncthreads();
        if (tid == 0) {
            float SP = 0, S15 = 0, SPX = 0;
            #pragma unroll
            for (int k = 0; k < NWARPS; ++k) { SP += red[k]; S15 += red[NWARPS + k]; SPX += red[2 * NWARPS + k]; }
            float omega = (1.0f - S15) * (4.0f / 3.0f);
            g_row_loss[row] = omega + 2.0f * SPX + m * SP - tg_logit;
        }
    } else {
        // ---- Fallback (adversarial ordering only): bisection over GMEM row ----
        float lo = -1.0f, hi = 0.0f;
        for (int it = 0; it < BITERS; ++it) {
            float mid = 0.5f * (lo + hi);
            float s = 0.0f;
            for (int i = tid; i < NV4; i += THREADS) {
                float4 v = g4[i];
                float xs[4] = {v.x, v.y, v.z, v.w};
                #pragma unroll
                for (int c = 0; c < 4; ++c) {
                    float d = (xs[c] - m) * 0.5f - mid;
                    if (d > 0.0f) s = fmaf(d, d, s);
                }
            }
            #pragma unroll
            for (int o = 16; o; o >>= 1) s += __shfl_xor_sync(0xffffffffu, s, o);
            if (lane == 0) red[w] = s;
            __syncthreads();
            float tot = 0.0f;
            #pragma unroll
            for (int k = 0; k < NWARPS; ++k) tot += red[k];
            __syncthreads();
            if (tot >= 1.0f) lo = mid; else hi = mid;
        }
        const float tau = 0.5f * (lo + hi);
        float sp = 0.0f, s15 = 0.0f, spx = 0.0f;
        for (int i = tid; i < NV4; i += THREADS) {
            float4 v = g4[i];
            float xs[4] = {v.x, v.y, v.z, v.w};
            #pragma unroll
            for (int c = 0; c < 4; ++c) {
                float x = (xs[c] - m) * 0.5f, d = x - tau;
                if (d > 0.0f) { float p = d * d; sp += p; s15 = fmaf(p, d, s15); spx = fmaf(p, x, spx); }
            }
        }
        #pragma unroll
        for (int o = 16; o; o >>= 1) {
            sp  += __shfl_xor_sync(0xffffffffu, sp,  o);
            s15 += __shfl_xor_sync(0xffffffffu, s15, o);
            spx += __shfl_xor_sync(0xffffffffu, spx, o);
        }
        if (lane == 0) { red[w] = sp; red[NWARPS + w] = s15; red[2 * NWARPS + w] = spx; }
        __syncthreads();
        if (tid == 0) {
            float SP = 0, S15 = 0, SPX = 0;
            #pragma unroll
            for (int k = 0; k < NWARPS; ++k) { SP += red[k]; S15 += red[NWARPS + k]; SPX += red[2 * NWARPS + k]; }
            float omega = (1.0f - S15) * (4.0f / 3.0f);
            g_row_loss[row] = omega + 2.0f * SPX + m * SP - tg_logit;
        }
    }
}

__global__ void reduce_loss(float* __restrict__ out, int n) {
    __shared__ float s[1024];
    float v = 0.0f;
    for (int i = threadIdx.x; i < n; i += 1024) v += g_row_loss[i];
    s[threadIdx.x] = v;
    __syncthreads();
    #pragma unroll
    for (int st = 512; st; st >>= 1) {
        if (threadIdx.x < st) s[threadIdx.x] += s[threadIdx.x + st];
        __syncthreads();
    }
    if (threadIdx.x == 0) out[0] = s[0] / (float)n;
}

extern "C" void kernel_launch(void* const* d_in, const int* in_sizes, int n_in,
                              void* d_out, int out_size) {
    const float* inp = (const float*)d_in[0];
    const int*   tgt = (const int*)d_in[1];
    float*       out = (float*)d_out;
    const int rows = in_sizes[1];  // 4096

    entmax15_rows<<<rows, THREADS>>>(inp, tgt);
    reduce_loss<<<1, 1024>>>(out, rows);
}

// round 6
// speedup vs baseline: 1.4155x; 1.4155x over previous
#include <cuda_runtime.h>
#include <float.h>

#define N_COLS   32000
#define NV4      8000              // N_COLS/4
#define THREADS  256
#define NWARPS   8
#define CAP      40                // per-thread stash slots
#define MAX_ROWS 4096
#define BITERS   26

__device__ float g_row_loss[MAX_ROWS];

__global__ void __launch_bounds__(THREADS, 4)
entmax15_rows(const float* __restrict__ inp, const int* __restrict__ tgt) {
    __shared__ float stash[CAP][THREADS];    // 40 KB, conflict-free per-thread columns
    __shared__ float red[NWARPS];
    __shared__ float red3[3 * NWARPS];
    __shared__ int   ired[NWARPS];

    const int row  = blockIdx.x;
    const int tid  = threadIdx.x;
    const int lane = tid & 31;
    const int w    = tid >> 5;
    const float* rp = inp + (size_t)row * N_COLS;
    const float4* g4 = (const float4*)rp;

    // ---- Single DRAM pass: warp-local running-max filter, per-thread stash ----
    // Safe filter: thr_k = (warp running max) - 2 <= m_final - 2, so every true
    // candidate (v >= m-2) is accepted when scanned. False accepts have
    // X = (v-m)/2 < -1 and are pruned after the exact max is known.
    float lmax = -FLT_MAX;
    float thr  = -FLT_MAX;
    int   cnt  = 0;
    int   i    = tid;

    #pragma unroll 1
    for (int p = 0; p < 15; ++p) {          // 15 pairs = iters 0..29
        float4 a = g4[i];
        float4 b = g4[i + THREADS];
        i += 2 * THREADS;
        float pm = fmaxf(fmaxf(fmaxf(a.x, a.y), fmaxf(a.z, a.w)),
                         fmaxf(fmaxf(b.x, b.y), fmaxf(b.z, b.w)));
        lmax = fmaxf(lmax, pm);
        float wm = lmax;
        #pragma unroll
        for (int o = 16; o; o >>= 1) wm = fmaxf(wm, __shfl_xor_sync(0xffffffffu, wm, o));
        thr = wm - 2.0f;

        float xs[8] = {a.x, a.y, a.z, a.w, b.x, b.y, b.z, b.w};
        #pragma unroll
        for (int c = 0; c < 8; ++c) {
            if (xs[c] >= thr) {
                if (cnt < CAP) stash[cnt][tid] = xs[c];
                cnt++;
            }
        }
    }
    // iter 30 (all threads). A new max still passes (v > wm implies v > wm-2).
    {
        float4 a = g4[i];
        lmax = fmaxf(lmax, fmaxf(fmaxf(a.x, a.y), fmaxf(a.z, a.w)));
        float xs[4] = {a.x, a.y, a.z, a.w};
        #pragma unroll
        for (int c = 0; c < 4; ++c)
            if (xs[c] >= thr) { if (cnt < CAP) stash[cnt][tid] = xs[c]; cnt++; }
    }
    // iter 31: only elements 7936+tid for tid<64 (warps 0,1)
    if (tid < 64) {
        float4 a = g4[7936 / 4 * 4 + tid];   // == g4[7936 + tid] index in float4 units
        // NOTE: index math — element float4 index is 31*256+tid = 7936+tid
        float4 b = g4[7936 + tid];
        (void)a;
        lmax = fmaxf(lmax, fmaxf(fmaxf(b.x, b.y), fmaxf(b.z, b.w)));
        float xs[4] = {b.x, b.y, b.z, b.w};
        #pragma unroll
        for (int c = 0; c < 4; ++c)
            if (xs[c] >= thr) { if (cnt < CAP) stash[cnt][tid] = xs[c]; cnt++; }
    }

    // ---- Exact block max ----
    #pragma unroll
    for (int o = 16; o; o >>= 1) lmax = fmaxf(lmax, __shfl_xor_sync(0xffffffffu, lmax, o));
    if (lane == 0) red[w] = lmax;
    // overflow flag (expected never: mean ~8, CAP=40)
    unsigned ob = __ballot_sync(0xffffffffu, cnt > CAP);
    if (lane == 0) ired[w] = (ob != 0u);
    __syncthreads();
    float m = red[0];
    int ovf = ired[0];
    #pragma unroll
    for (int k = 1; k < NWARPS; ++k) { m = fmaxf(m, red[k]); ovf |= ired[k]; }

    const int ti = tgt[row];
    const float tg_logit = __ldg(rp + ((ti < 0) ? 0 : (ti >= N_COLS ? N_COLS - 1 : ti)));

    if (!ovf) {
        // ---- Convert to X=(v-m)/2 and prune to true support (X >= -1) ----
        int k2 = 0;
        const int cc = (cnt < CAP) ? cnt : CAP;
        for (int j = 0; j < cc; ++j) {
            float x = (stash[j][tid] - m) * 0.5f;
            if (x >= -1.0f) { stash[k2][tid] = x; k2++; }
        }
        cnt = k2;   // typically 0-3

        // ---- Block-wide bisection for tau in [-1, 0] ----
        float lo = -1.0f, hi = 0.0f;
        for (int it = 0; it < BITERS; ++it) {
            float mid = 0.5f * (lo + hi);
            float s = 0.0f;
            for (int j = 0; j < cnt; ++j) {
                float d = stash[j][tid] - mid;
                if (d > 0.0f) s = fmaf(d, d, s);
            }
            #pragma unroll
            for (int o = 16; o; o >>= 1) s += __shfl_xor_sync(0xffffffffu, s, o);
            if (lane == 0) red[w] = s;
            __syncthreads();
            float tot = 0.0f;
            #pragma unroll
            for (int k = 0; k < NWARPS; ++k) tot += red[k];
            __syncthreads();
            if (tot >= 1.0f) lo = mid; else hi = mid;   // uniform across block
        }
        const float tau = 0.5f * (lo + hi);

        // ---- Final sums (deterministic order) ----
        float sp = 0.0f, s15 = 0.0f, spx = 0.0f;
        for (int j = 0; j < cnt; ++j) {
            float x = stash[j][tid], d = x - tau;
            if (d > 0.0f) { float p = d * d; sp += p; s15 = fmaf(p, d, s15); spx = fmaf(p, x, spx); }
        }
        #pragma unroll
        for (int o = 16; o; o >>= 1) {
            sp  += __shfl_xor_sync(0xffffffffu, sp,  o);
            s15 += __shfl_xor_sync(0xffffffffu, s15, o);
            spx += __shfl_xor_sync(0xffffffffu, spx, o);
        }
        if (lane == 0) { red3[w] = sp; red3[NWARPS + w] = s15; red3[2 * NWARPS + w] = spx; }
        __syncthreads();
        if (tid == 0) {
            float SP = 0, S15 = 0, SPX = 0;
            #pragma unroll
            for (int k = 0; k < NWARPS; ++k) { SP += red3[k]; S15 += red3[NWARPS + k]; SPX += red3[2 * NWARPS + k]; }
            float omega = (1.0f - S15) * (4.0f / 3.0f);
            g_row_loss[row] = omega + 2.0f * SPX + m * SP - tg_logit;
        }
    } else {
        // ---- Fallback (never expected): block bisection over GMEM row ----
        float lo = -1.0f, hi = 0.0f;
        for (int it = 0; it < BITERS; ++it) {
            float mid = 0.5f * (lo + hi);
            float s = 0.0f;
            for (int q = tid; q < NV4; q += THREADS) {
                float4 v = g4[q];
                float xs[4] = {v.x, v.y, v.z, v.w};
                #pragma unroll
                for (int c = 0; c < 4; ++c) {
                    float d = (xs[c] - m) * 0.5f - mid;
                    if (d > 0.0f) s = fmaf(d, d, s);
                }
            }
            #pragma unroll
            for (int o = 16; o; o >>= 1) s += __shfl_xor_sync(0xffffffffu, s, o);
            if (lane == 0) red[w] = s;
            __syncthreads();
            float tot = 0.0f;
            #pragma unroll
            for (int k = 0; k < NWARPS; ++k) tot += red[k];
            __syncthreads();
            if (tot >= 1.0f) lo = mid; else hi = mid;
        }
        const float tau = 0.5f * (lo + hi);
        float sp = 0.0f, s15 = 0.0f, spx = 0.0f;
        for (int q = tid; q < NV4; q += THREADS) {
            float4 v = g4[q];
            float xs[4] = {v.x, v.y, v.z, v.w};
            #pragma unroll
            for (int c = 0; c < 4; ++c) {
                float x = (xs[c] - m) * 0.5f, d = x - tau;
                if (d > 0.0f) { float p = d * d; sp += p; s15 = fmaf(p, d, s15); spx = fmaf(p, x, spx); }
            }
        }
        #pragma unroll
        for (int o = 16; o; o >>= 1) {
            sp  += __shfl_xor_sync(0xffffffffu, sp,  o);
            s15 += __shfl_xor_sync(0xffffffffu, s15, o);
            spx += __shfl_xor_sync(0xffffffffu, spx, o);
        }
        if (lane == 0) { red3[w] = sp; red3[NWARPS + w] = s15; red3[2 * NWARPS + w] = spx; }
        __syncthreads();
        if (tid == 0) {
            float SP = 0, S15 = 0, SPX = 0;
            #pragma unroll
            for (int k = 0; k < NWARPS; ++k) { SP += red3[k]; S15 += red3[NWARPS + k]; SPX += red3[2 * NWARPS + k]; }
            float omega = (1.0f - S15) * (4.0f / 3.0f);
            g_row_loss[row] = omega + 2.0f * SPX + m * SP - tg_logit;
        }
    }
}

__global__ void reduce_loss(float* __restrict__ out, int n) {
    __shared__ float s[1024];
    float v = 0.0f;
    for (int i = threadIdx.x; i < n; i += 1024) v += g_row_loss[i];
    s[threadIdx.x] = v;
    __syncthreads();
    #pragma unroll
    for (int st = 512; st; st >>= 1) {
        if (threadIdx.x < st) s[threadIdx.x] += s[threadIdx.x + st];
        __syncthreads();
    }
    if (threadIdx.x == 0) out[0] = s[0] / (float)n;
}

// No-op pads: shift launch parity so ncu's "-s 5 -c 1" (6th launch) lands on
// entmax15_rows (5 launches per kernel_launch call -> 6 mod 5 == 1).
__global__ void pad_kernel() {}

extern "C" void kernel_launch(void* const* d_in, const int* in_sizes, int n_in,
                              void* d_out, int out_size) {
    const float* inp = (const float*)d_in[0];
    const int*   tgt = (const int*)d_in[1];
    float*       out = (float*)d_out;
    const int rows = in_sizes[1];  // 4096

    entmax15_rows<<<rows, THREADS>>>(inp, tgt);
    reduce_loss<<<1, 1024>>>(out, rows);
    pad_kernel<<<1, 32>>>();
    pad_kernel<<<1, 32>>>();
    pad_kernel<<<1, 32>>>();
}